// round 1
// baseline (speedup 1.0000x reference)
#include <cuda_runtime.h>
#include <math.h>

#define B_DIM 4096
#define C_DIM 5000
#define G4    1250                 // float4 groups per row (5000/4)
#define THREADS 512
#define BLOCKS  256
#define ROWS_PER_BLOCK (B_DIM / BLOCKS)   // 16
#define GPT 3                      // groups per thread: ceil(1250/512)

__device__ float  g_col_neg[C_DIM];
__device__ float  g_col_pos[C_DIM];
__device__ double g_row_loss;

__device__ __forceinline__ float softplus_f(float z) {
    // safe softplus; z here is ~40, branch predicts trivially
    return (z > 20.f) ? z : log1pf(__expf(z));
}

__global__ void zero_kernel() {
    int i = blockIdx.x * blockDim.x + threadIdx.x;
    if (i < C_DIM) { g_col_neg[i] = 0.f; g_col_pos[i] = 0.f; }
    if (i == 0) g_row_loss = 0.0;
}

__global__ __launch_bounds__(THREADS)
void twl_main_kernel(const float* __restrict__ logits,
                     const int*   __restrict__ targets) {
    __shared__ float s_n[16];
    __shared__ float s_p[16];
    const int t    = threadIdx.x;
    const int warp = t >> 5;
    const int lane = t & 31;

    // Column partial sums, register-resident: thread t owns float4-groups
    // t, t+512, t+1024 for ALL rows of this block.
    float cn[GPT][4];
    float cp[GPT][4];
    #pragma unroll
    for (int j = 0; j < GPT; ++j)
        #pragma unroll
        for (int k = 0; k < 4; ++k) { cn[j][k] = 0.f; cp[j][k] = 0.f; }

    double blk_loss = 0.0;
    const int row0 = blockIdx.x * ROWS_PER_BLOCK;

    for (int r = 0; r < ROWS_PER_BLOCK; ++r) {
        const int row = row0 + r;
        const float4* __restrict__ lrow =
            reinterpret_cast<const float4*>(logits + (size_t)row * C_DIM);
        const int4* __restrict__ trow =
            reinterpret_cast<const int4*>(targets + (size_t)row * C_DIM);

        float rn = 0.f, rp = 0.f;

        #pragma unroll
        for (int j = 0; j < GPT; ++j) {
            const int g = t + j * THREADS;
            if (g < G4) {
                const float4 x  = lrow[g];
                const int4   tg = trow[g];

                #define PROC(XX, TT, K)                                        \
                do {                                                           \
                    const bool pos = ((TT) == 1);                              \
                    const bool neg = ((TT) == 0);                              \
                    const float a  = (XX) * (pos ? -0.25f : 1.0f);             \
                    const float e  = __expf(a);                                \
                    const float en = neg ? e : 0.f;                            \
                    const float ep = pos ? e : 0.f;                            \
                    rn += en; rp += ep;                                        \
                    cn[j][K] += en; cp[j][K] += ep;                            \
                } while (0)

                PROC(x.x, tg.x, 0);
                PROC(x.y, tg.y, 1);
                PROC(x.z, tg.z, 2);
                PROC(x.w, tg.w, 3);
                #undef PROC
            }
        }

        // block-wide reduce of (rn, rp): warp shuffle then cross-warp via smem
        #pragma unroll
        for (int o = 16; o > 0; o >>= 1) {
            rn += __shfl_down_sync(0xffffffffu, rn, o);
            rp += __shfl_down_sync(0xffffffffu, rp, o);
        }
        if (lane == 0) { s_n[warp] = rn; s_p[warp] = rp; }
        __syncthreads();
        if (warp == 0) {
            float vn = (lane < 16) ? s_n[lane] : 0.f;
            float vp = (lane < 16) ? s_p[lane] : 0.f;
            #pragma unroll
            for (int o = 8; o > 0; o >>= 1) {
                vn += __shfl_down_sync(0xffffffffu, vn, o);
                vp += __shfl_down_sync(0xffffffffu, vp, o);
            }
            if (lane == 0) {
                if (vn > 0.f && vp > 0.f) {
                    // lse_neg = log(sum_neg exp(x)); lse_pos = 4*log(sum_pos exp(-x/4))
                    const float z = __logf(vn) + 4.f * __logf(vp);
                    blk_loss += (double)softplus_f(z);
                }
            }
        }
        __syncthreads();   // protect s_n/s_p reuse next row
    }

    if (t == 0) atomicAdd(&g_row_loss, blk_loss);

    // flush register column partials (one contribution per block per column)
    #pragma unroll
    for (int j = 0; j < GPT; ++j) {
        const int g = t + j * THREADS;
        if (g < G4) {
            #pragma unroll
            for (int k = 0; k < 4; ++k) {
                atomicAdd(&g_col_neg[4 * g + k], cn[j][k]);
                atomicAdd(&g_col_pos[4 * g + k], cp[j][k]);
            }
        }
    }
}

__global__ __launch_bounds__(1024)
void finalize_kernel(float* __restrict__ out) {
    __shared__ double sd[32];
    const int t = threadIdx.x;

    double s = 0.0;
    for (int c = t; c < C_DIM; c += 1024) {
        const float sn = g_col_neg[c];
        const float sp = g_col_pos[c];
        if (sn > 0.f && sp > 0.f) {
            const float z = __logf(sn) + 4.f * __logf(sp);
            s += (double)softplus_f(z);
        }
    }
    #pragma unroll
    for (int o = 16; o > 0; o >>= 1)
        s += __shfl_down_sync(0xffffffffu, s, o);
    if ((t & 31) == 0) sd[t >> 5] = s;
    __syncthreads();
    if (t < 32) {
        double v = sd[t];
        #pragma unroll
        for (int o = 16; o > 0; o >>= 1)
            v += __shfl_down_sync(0xffffffffu, v, o);
        if (t == 0) {
            const double row_mean = g_row_loss / (double)B_DIM;
            const double col_mean = v / (double)C_DIM;
            out[0] = (float)(0.5 * (row_mean + col_mean));
        }
    }
}

extern "C" void kernel_launch(void* const* d_in, const int* in_sizes, int n_in,
                              void* d_out, int out_size) {
    const float* logits  = (const float*)d_in[0];
    const int*   targets = (const int*)d_in[1];
    float* out = (float*)d_out;

    zero_kernel<<<(C_DIM + 255) / 256, 256>>>();
    twl_main_kernel<<<BLOCKS, THREADS>>>(logits, targets);
    finalize_kernel<<<1, 1024>>>(out);
}

// round 2
// speedup vs baseline: 1.0065x; 1.0065x over previous
#include <cuda_runtime.h>
#include <math.h>

#define B_DIM 4096
#define C_DIM 5000
#define G4    1250                 // float4 groups per row (5000/4)
#define THREADS 512
#define BLOCKS  256
#define ROWS_PER_BLOCK (B_DIM / BLOCKS)   // 16
#define GPT 3                      // groups per thread: ceil(1250/512)

__device__ float  g_col_neg[C_DIM];
__device__ float  g_col_pos[C_DIM];
__device__ double g_row_loss;

__device__ __forceinline__ float softplus_f(float z) {
    // safe softplus; z here is ~40, branch predicts trivially
    return (z > 20.f) ? z : log1pf(__expf(z));
}

__global__ void zero_kernel() {
    int i = blockIdx.x * blockDim.x + threadIdx.x;
    if (i < C_DIM) { g_col_neg[i] = 0.f; g_col_pos[i] = 0.f; }
    if (i == 0) g_row_loss = 0.0;
}

__global__ __launch_bounds__(THREADS)
void twl_main_kernel(const float* __restrict__ logits,
                     const int*   __restrict__ targets) {
    __shared__ float s_n[16];
    __shared__ float s_p[16];
    const int t    = threadIdx.x;
    const int warp = t >> 5;
    const int lane = t & 31;

    // Column partial sums, register-resident: thread t owns float4-groups
    // t, t+512, t+1024 for ALL rows of this block.
    float cn[GPT][4];
    float cp[GPT][4];
    #pragma unroll
    for (int j = 0; j < GPT; ++j)
        #pragma unroll
        for (int k = 0; k < 4; ++k) { cn[j][k] = 0.f; cp[j][k] = 0.f; }

    double blk_loss = 0.0;
    const int row0 = blockIdx.x * ROWS_PER_BLOCK;

    for (int r = 0; r < ROWS_PER_BLOCK; ++r) {
        const int row = row0 + r;
        const float4* __restrict__ lrow =
            reinterpret_cast<const float4*>(logits + (size_t)row * C_DIM);
        const int4* __restrict__ trow =
            reinterpret_cast<const int4*>(targets + (size_t)row * C_DIM);

        float rn = 0.f, rp = 0.f;

        #pragma unroll
        for (int j = 0; j < GPT; ++j) {
            const int g = t + j * THREADS;
            if (g < G4) {
                const float4 x  = lrow[g];
                const int4   tg = trow[g];

                #define PROC(XX, TT, K)                                        \
                do {                                                           \
                    const bool pos = ((TT) == 1);                              \
                    const bool neg = ((TT) == 0);                              \
                    const float a  = (XX) * (pos ? -0.25f : 1.0f);             \
                    const float e  = __expf(a);                                \
                    const float en = neg ? e : 0.f;                            \
                    const float ep = pos ? e : 0.f;                            \
                    rn += en; rp += ep;                                        \
                    cn[j][K] += en; cp[j][K] += ep;                            \
                } while (0)

                PROC(x.x, tg.x, 0);
                PROC(x.y, tg.y, 1);
                PROC(x.z, tg.z, 2);
                PROC(x.w, tg.w, 3);
                #undef PROC
            }
        }

        // block-wide reduce of (rn, rp): warp shuffle then cross-warp via smem
        #pragma unroll
        for (int o = 16; o > 0; o >>= 1) {
            rn += __shfl_down_sync(0xffffffffu, rn, o);
            rp += __shfl_down_sync(0xffffffffu, rp, o);
        }
        if (lane == 0) { s_n[warp] = rn; s_p[warp] = rp; }
        __syncthreads();
        if (warp == 0) {
            float vn = (lane < 16) ? s_n[lane] : 0.f;
            float vp = (lane < 16) ? s_p[lane] : 0.f;
            #pragma unroll
            for (int o = 8; o > 0; o >>= 1) {
                vn += __shfl_down_sync(0xffffffffu, vn, o);
                vp += __shfl_down_sync(0xffffffffu, vp, o);
            }
            if (lane == 0) {
                if (vn > 0.f && vp > 0.f) {
                    // lse_neg = log(sum_neg exp(x)); lse_pos = 4*log(sum_pos exp(-x/4))
                    const float z = __logf(vn) + 4.f * __logf(vp);
                    blk_loss += (double)softplus_f(z);
                }
            }
        }
        __syncthreads();   // protect s_n/s_p reuse next row
    }

    if (t == 0) atomicAdd(&g_row_loss, blk_loss);

    // flush register column partials (one contribution per block per column)
    #pragma unroll
    for (int j = 0; j < GPT; ++j) {
        const int g = t + j * THREADS;
        if (g < G4) {
            #pragma unroll
            for (int k = 0; k < 4; ++k) {
                atomicAdd(&g_col_neg[4 * g + k], cn[j][k]);
                atomicAdd(&g_col_pos[4 * g + k], cp[j][k]);
            }
        }
    }
}

__global__ __launch_bounds__(1024)
void finalize_kernel(float* __restrict__ out) {
    __shared__ double sd[32];
    const int t = threadIdx.x;

    double s = 0.0;
    for (int c = t; c < C_DIM; c += 1024) {
        const float sn = g_col_neg[c];
        const float sp = g_col_pos[c];
        if (sn > 0.f && sp > 0.f) {
            const float z = __logf(sn) + 4.f * __logf(sp);
            s += (double)softplus_f(z);
        }
    }
    #pragma unroll
    for (int o = 16; o > 0; o >>= 1)
        s += __shfl_down_sync(0xffffffffu, s, o);
    if ((t & 31) == 0) sd[t >> 5] = s;
    __syncthreads();
    if (t < 32) {
        double v = sd[t];
        #pragma unroll
        for (int o = 16; o > 0; o >>= 1)
            v += __shfl_down_sync(0xffffffffu, v, o);
        if (t == 0) {
            const double row_mean = g_row_loss / (double)B_DIM;
            const double col_mean = v / (double)C_DIM;
            out[0] = (float)(0.5 * (row_mean + col_mean));
        }
    }
}

extern "C" void kernel_launch(void* const* d_in, const int* in_sizes, int n_in,
                              void* d_out, int out_size) {
    const float* logits  = (const float*)d_in[0];
    const int*   targets = (const int*)d_in[1];
    float* out = (float*)d_out;

    zero_kernel<<<(C_DIM + 255) / 256, 256>>>();
    twl_main_kernel<<<BLOCKS, THREADS>>>(logits, targets);
    finalize_kernel<<<1, 1024>>>(out);
}